// round 14
// baseline (speedup 1.0000x reference)
#include <cuda_runtime.h>
#include <cuda_bf16.h>
#include <cuda_fp16.h>
#include <math.h>
#include <stdint.h>

#define BATCH 4096
#define HID 128
#define NSTEP 16

// ---------------- global data (device globals; no allocations) ---------------
__device__ __align__(16) __nv_bfloat16 d_W_hi[512 * 192];   // reordered cols: n' = j*4+gate
__device__ __align__(16) __nv_bfloat16 d_W_lo[512 * 192];
__device__ __align__(16) float d_bias[512];                  // reordered
__device__ __align__(16) __half d_img_h[(size_t)BATCH * 2 * 4096];  // fp16 images (67MB)

// ---------------- smem layout of the mega kernel (bytes) ---------------------
// x:  [32][72] bf16 (cols 0-63 valid), stride 144      @0 hi, @4608 lo
// h:  TWO ping-pong buffers (read t&1, write (t+1)&1). Each buf = hi 8704 + lo 8704.
//     buf k: hi @ 9216 + k*17408, lo @ +8704. [32][136] bf16, stride 272.
// c:  [32][128] f32 @44032
// img: 8 warps x 2 bufs x 8192 @60416 (64 rows x 128B, XOR-swizzled 16B chunks)
// filt: 8 warps x 4608 @191488 (FhA 16x144 @+0; FwB @+2304: hi 8x144, lo @+1152)
// B bufs overlay filt: 2 x 18432 ([128][72] bf16, stride 144)
#define SX_HI   0
#define SX_LO   4608
#define SH0     9216
#define HBUF    17408
#define SC      44032
#define SIMG    60416
#define SFILT   191488
#define SB      191488
#define SM_TOTAL 228352

// ---------------- helpers ----------------------------------------------------
__device__ __forceinline__ uint32_t smem_u32(const void* p) {
    uint32_t a;
    asm("{ .reg .u64 t; cvta.to.shared.u64 t, %1; cvt.u32.u64 %0, t; }" : "=r"(a) : "l"(p));
    return a;
}
__device__ __forceinline__ void cp_async16(uint32_t dst, const void* src) {
    asm volatile("cp.async.cg.shared.global [%0], [%1], 16;" :: "r"(dst), "l"(src) : "memory");
}
__device__ __forceinline__ void cp_commit() {
    asm volatile("cp.async.commit_group;" ::: "memory");
}
template <int N>
__device__ __forceinline__ void cp_wait() {
    asm volatile("cp.async.wait_group %0;" :: "n"(N) : "memory");
}
__device__ __forceinline__ void ldm_x4(uint32_t* r, uint32_t a) {
    asm volatile("ldmatrix.sync.aligned.m8n8.x4.shared.b16 {%0,%1,%2,%3}, [%4];"
                 : "=r"(r[0]), "=r"(r[1]), "=r"(r[2]), "=r"(r[3]) : "r"(a));
}
__device__ __forceinline__ void ldm_x4_t(uint32_t* r, uint32_t a) {
    asm volatile("ldmatrix.sync.aligned.m8n8.x4.trans.shared.b16 {%0,%1,%2,%3}, [%4];"
                 : "=r"(r[0]), "=r"(r[1]), "=r"(r[2]), "=r"(r[3]) : "r"(a));
}
__device__ __forceinline__ void ldm_x2(uint32_t* r, uint32_t a) {
    asm volatile("ldmatrix.sync.aligned.m8n8.x2.shared.b16 {%0,%1}, [%2];"
                 : "=r"(r[0]), "=r"(r[1]) : "r"(a));
}
__device__ __forceinline__ void mma_bf16(float* d, const uint32_t* a, const uint32_t* b) {
    asm volatile(
        "mma.sync.aligned.m16n8k16.row.col.f32.bf16.bf16.f32 "
        "{%0,%1,%2,%3}, {%4,%5,%6,%7}, {%8,%9}, {%0,%1,%2,%3};"
        : "+f"(d[0]), "+f"(d[1]), "+f"(d[2]), "+f"(d[3])
        : "r"(a[0]), "r"(a[1]), "r"(a[2]), "r"(a[3]), "r"(b[0]), "r"(b[1]));
}
__device__ __forceinline__ void mma_f16(float* d, const uint32_t* a, const uint32_t* b) {
    asm volatile(
        "mma.sync.aligned.m16n8k16.row.col.f32.f16.f16.f32 "
        "{%0,%1,%2,%3}, {%4,%5,%6,%7}, {%8,%9}, {%0,%1,%2,%3};"
        : "+f"(d[0]), "+f"(d[1]), "+f"(d[2]), "+f"(d[3])
        : "r"(a[0]), "r"(a[1]), "r"(a[2]), "r"(a[3]), "r"(b[0]), "r"(b[1]));
}
__device__ __forceinline__ uint32_t pack_h2(float x, float y) {
    __half2 h = __floats2half2_rn(x, y);
    return *reinterpret_cast<uint32_t*>(&h);
}

// ---------------- prologue ---------------------------------------------------
// blocks [0,8192): img fp32->fp16; [8192,8576): weight reorder + split
__global__ void prologue_kernel(const float* __restrict__ imgs,
                                const float* __restrict__ W_ih,
                                const float* __restrict__ W_hh,
                                const float* __restrict__ b_ih,
                                const float* __restrict__ b_hh) {
    int bid = blockIdx.x, tid = threadIdx.x;
    if (bid < 8192) {
        const float4* in4 = reinterpret_cast<const float4*>(imgs);
        uint2* out2 = reinterpret_cast<uint2*>(d_img_h);
        for (int i = bid * 256 + tid; i < 8388608; i += 8192 * 256) {
            float4 v = in4[i];
            __half2 a = __floats2half2_rn(v.x, v.y);
            __half2 c = __floats2half2_rn(v.z, v.w);
            uint2 o;
            o.x = *reinterpret_cast<uint32_t*>(&a);
            o.y = *reinterpret_cast<uint32_t*>(&c);
            out2[i] = o;
        }
    } else {
        int idx = (bid - 8192) * 256 + tid;  // exactly 512*192
        int np = idx / 192, k = idx % 192;
        int gate = np & 3, j = np >> 2;
        int orig = gate * 128 + j;
        float w = (k < 64) ? W_ih[orig * 64 + k] : W_hh[orig * 128 + (k - 64)];
        __nv_bfloat16 hi = __float2bfloat16(w);
        __nv_bfloat16 lo = __float2bfloat16(w - __bfloat162float(hi));
        d_W_hi[np * 192 + k] = hi;
        d_W_lo[np * 192 + k] = lo;
        if (k == 0) d_bias[np] = b_ih[orig] + b_hh[orig];
    }
}

// ---------------- persistent mega kernel -------------------------------------
// grid 128 CTAs x 256 threads (8 warps). CTA owns samples [bid*32, bid*32+32).
// All 16 steps, no global sync. h double-buffered by step parity so the gates
// GEMM of step t never reads an h column already overwritten with h_{t+1}.
__global__ __launch_bounds__(256) void arc_kernel(
    float* __restrict__ out,
    const float* __restrict__ W_g, const float* __restrict__ b_g)
{
    extern __shared__ char sm[];
    uint32_t sb = smem_u32(sm);
    int tid = threadIdx.x, wid = tid >> 5, lane = tid & 31;
    int wm = wid & 1, wn = wid >> 1;
    int bm0 = blockIdx.x * 32;

    __nv_bfloat16* s_xhi = reinterpret_cast<__nv_bfloat16*>(sm + SX_HI);
    __nv_bfloat16* s_xlo = reinterpret_cast<__nv_bfloat16*>(sm + SX_LO);
    float* s_c = reinterpret_cast<float*>(sm + SC);

    const int tva[3] = {0, 0, 1};
    const int tvb[3] = {0, 1, 0};

    // zero state (x, both h buffers, c): 60416 bytes
    for (int i = tid; i < 60416 / 4; i += 256)
        reinterpret_cast<float*>(sm)[i] = 0.0f;

#define ISSUE_IMG(pbuf, smp, selv) do {                                          \
        const __half* src_ = d_img_h + ((size_t)(smp) * 2 + (size_t)(selv)) * 4096; \
        uint32_t dst_ = sb + SIMG + (wid * 2 + (pbuf)) * 8192;                   \
        _Pragma("unroll")                                                        \
        for (int j_ = 0; j_ < 16; j_++) {                                        \
            int cc_ = lane + j_ * 32;                                            \
            int rr_ = cc_ >> 3, ch_ = cc_ & 7;                                   \
            cp_async16(dst_ + rr_ * 128 + ((ch_ ^ (rr_ & 7)) * 16),              \
                       src_ + rr_ * 64 + ch_ * 8);                               \
        }                                                                        \
        cp_commit();                                                             \
    } while (0)

    // prefetch round-0 image of step 0
    ISSUE_IMG(0, bm0 + wid * 4, 0);
    __syncthreads();

    for (int t = 0; t < NSTEP; t++) {
        int sel = t & 1;
        uint32_t h_rd = (uint32_t)(SH0 + (t & 1) * HBUF);          // read h_t
        uint32_t h_wr = (uint32_t)(SH0 + ((t + 1) & 1) * HBUF);    // write h_{t+1}
        __nv_bfloat16* s_hhi_w = reinterpret_cast<__nv_bfloat16*>(sm + h_wr);
        __nv_bfloat16* s_hlo_w = reinterpret_cast<__nv_bfloat16*>(sm + h_wr + 8704);

        // ================= phase G: glimpse (per-warp, 4 rounds) =============
        uint32_t filtb = sb + SFILT + wid * 4608;
        for (int r = 0; r < 4; r++) {
            int s_loc = wid * 4 + r;
            int pbuf = r & 1;
            if (r < 3) ISSUE_IMG(pbuf ^ 1, bm0 + s_loc + 1, sel);

            // gp = tanh(h @ W_g^T + b_g), h = hi + lo from read buffer
            float h4[4];
            {
                uint2 rhu = *reinterpret_cast<uint2*>(sm + h_rd + s_loc * 272 + lane * 8);
                uint2 rlu = *reinterpret_cast<uint2*>(sm + h_rd + 8704 + s_loc * 272 + lane * 8);
                __nv_bfloat162* hh = reinterpret_cast<__nv_bfloat162*>(&rhu);
                __nv_bfloat162* ll = reinterpret_cast<__nv_bfloat162*>(&rlu);
                float2 h01 = __bfloat1622float2(hh[0]);
                float2 h23 = __bfloat1622float2(hh[1]);
                float2 l01 = __bfloat1622float2(ll[0]);
                float2 l23 = __bfloat1622float2(ll[1]);
                h4[0] = h01.x + l01.x; h4[1] = h01.y + l01.y;
                h4[2] = h23.x + l23.x; h4[3] = h23.y + l23.y;
            }
            float gp[3];
#pragma unroll
            for (int k = 0; k < 3; k++) {
                float4 wv = __ldg(reinterpret_cast<const float4*>(&W_g[k * 128 + lane * 4]));
                float p = h4[0] * wv.x + h4[1] * wv.y + h4[2] * wv.z + h4[3] * wv.w;
#pragma unroll
                for (int o = 16; o > 0; o >>= 1) p += __shfl_xor_sync(0xffffffffu, p, o);
                gp[k] = tanhf(p + __ldg(&b_g[k]));
            }

            // normalized Cauchy filterbanks, fp16 hi/lo
            {
                float ad  = fabsf(gp[2]);
                float dlt = 8.0f * (1.0f - ad);
                float gam = expf(1.0f - 2.0f * ad);
                float ig  = 1.0f / gam;
                float cpre = 1.0f / (3.14159265358979323f * gam);
                float fi0 = (float)(2 * lane), fi1 = fi0 + 1.0f;
#pragma unroll
                for (int a = 0; a < 2; a++) {
                    float center = 31.5f * (gp[a] + 1.0f);
                    uint32_t base = filtb + (a ? 2304u : 0u);
#pragma unroll
                    for (int tt = 0; tt < 8; tt++) {
                        float gpix = center + dlt * ((float)tt - 3.5f);
                        float u0 = (fi0 - gpix) * ig, u1 = (fi1 - gpix) * ig;
                        float v0 = __fdividef(cpre, 1.0f + u0 * u0);
                        float v1 = __fdividef(cpre, 1.0f + u1 * u1);
                        float s = v0 + v1;
#pragma unroll
                        for (int o = 16; o > 0; o >>= 1) s += __shfl_xor_sync(0xffffffffu, s, o);
                        float inv = __fdividef(1.0f, s + 1e-4f);
                        v0 *= inv; v1 *= inv;
                        uint32_t hi2 = pack_h2(v0, v1);
                        __half2 hh2 = *reinterpret_cast<__half2*>(&hi2);
                        float2 hf = __half22float2(hh2);
                        uint32_t lo2 = pack_h2(v0 - hf.x, v1 - hf.y);
                        uint32_t dst = base + tt * 144 + lane * 4;
                        asm volatile("st.shared.b32 [%0], %1;" :: "r"(dst), "r"(hi2));
                        asm volatile("st.shared.b32 [%0], %1;" :: "r"(dst + 1152), "r"(lo2));
                    }
                }
            }
            if (r < 3) cp_wait<1>(); else cp_wait<0>();
            __syncwarp();

            // G1: A = FhA packed (rows 0-7 hi, 8-15 lo); B = img via trans ldm
            float acc[8][4];
#pragma unroll
            for (int nt = 0; nt < 8; nt++)
#pragma unroll
                for (int q = 0; q < 4; q++) acc[nt][q] = 0.0f;

            uint32_t fh = filtb + (lane & 15) * 144 + (lane >> 4) * 16;
            uint32_t ibuf = sb + SIMG + (wid * 2 + pbuf) * 8192 + (lane & 15) * 128;
            int cb = lane >> 4, xorv = lane & 7;

#pragma unroll
            for (int kk = 0; kk < 4; kk++) {
                uint32_t ah[4];
                ldm_x4(ah, fh + kk * 32);
#pragma unroll
                for (int nt2 = 0; nt2 < 4; nt2++) {
                    uint32_t bb[4];
                    uint32_t ch = (uint32_t)(((2 * nt2 + cb) ^ xorv) * 16);
                    ldm_x4_t(bb, ibuf + kk * 2048 + ch);
                    mma_f16(acc[2 * nt2],     ah, bb);
                    mma_f16(acc[2 * nt2 + 1], ah, bb + 2);
                }
            }

            float ps[8][2];
#pragma unroll
            for (int nt = 0; nt < 8; nt++) {
                ps[nt][0] = acc[nt][0] + acc[nt][2];
                ps[nt][1] = acc[nt][1] + acc[nt][3];
            }

            // G2
            float acc2[4] = {0.0f, 0.0f, 0.0f, 0.0f};
            uint32_t fwb = filtb + 2304 + (lane & 7) * 144 + ((lane >> 3) & 1) * 16;
#pragma unroll
            for (int kk2 = 0; kk2 < 4; kk2++) {
                float p0 = ps[2 * kk2][0],     p1 = ps[2 * kk2][1];
                float q0 = ps[2 * kk2 + 1][0], q1 = ps[2 * kk2 + 1][1];
                uint32_t ah[4], al[4];
                ah[0] = pack_h2(p0, p1);
                ah[2] = pack_h2(q0, q1);
                ah[1] = 0u; ah[3] = 0u;
                {
                    __half2 h0 = *reinterpret_cast<__half2*>(&ah[0]);
                    __half2 h2 = *reinterpret_cast<__half2*>(&ah[2]);
                    float2 f0 = __half22float2(h0);
                    float2 f2 = __half22float2(h2);
                    al[0] = pack_h2(p0 - f0.x, p1 - f0.y);
                    al[2] = pack_h2(q0 - f2.x, q1 - f2.y);
                    al[1] = 0u; al[3] = 0u;
                }
                uint32_t bh[2], bl[2];
                ldm_x2(bh, fwb + kk2 * 32);
                ldm_x2(bl, fwb + 1152 + kk2 * 32);
                mma_f16(acc2, ah, bh);
                mma_f16(acc2, al, bh);
                mma_f16(acc2, ah, bl);
            }

            // write x to smem (hi/lo bf16)
            {
                int c8 = (lane >> 2) * 8 + (lane & 3) * 2;
                float v0 = acc2[0], v1 = acc2[1];
                __nv_bfloat16 h0 = __float2bfloat16(v0);
                __nv_bfloat16 h1 = __float2bfloat16(v1);
                s_xhi[s_loc * 72 + c8]     = h0;
                s_xhi[s_loc * 72 + c8 + 1] = h1;
                s_xlo[s_loc * 72 + c8]     = __float2bfloat16(v0 - __bfloat162float(h0));
                s_xlo[s_loc * 72 + c8 + 1] = __float2bfloat16(v1 - __bfloat162float(h1));
            }
        }
        __syncthreads();

        // ================= phase M: gates GEMM + LSTM ========================
        if (t < NSTEP - 1) ISSUE_IMG(0, bm0 + wid * 4, sel ^ 1);

#define LOAD_B(c9v, bufv, ncv) do {                                              \
        int t2_ = (c9v) / 3, kb2_ = (c9v) % 3;                                   \
        const __nv_bfloat16* ws_ = tvb[t2_] ? d_W_lo : d_W_hi;                   \
        _Pragma("unroll")                                                        \
        for (int p_ = 0; p_ < 4; p_++) {                                         \
            int ix_ = tid + p_ * 256;                                            \
            int rw_ = ix_ >> 3, cc_ = ix_ & 7;                                   \
            cp_async16(sb + SB + (bufv) * 18432 + rw_ * 144 + cc_ * 16,          \
                       ws_ + ((ncv) * 128 + rw_) * 192 + kb2_ * 64 + cc_ * 8);   \
        }                                                                        \
        cp_commit();                                                             \
    } while (0)

        for (int nc = 0; nc < 4; nc++) {
            float acc[4][4];
#pragma unroll
            for (int nt = 0; nt < 4; nt++)
#pragma unroll
                for (int q = 0; q < 4; q++) acc[nt][q] = 0.0f;

            LOAD_B(0, 0, nc);
            for (int c9 = 0; c9 < 9; c9++) {
                int buf = c9 & 1;
                if (c9 < 8) LOAD_B(c9 + 1, buf ^ 1, nc);
                if (c9 < 8) cp_wait<1>(); else cp_wait<0>();
                __syncthreads();

                int t_ = c9 / 3, kb = c9 % 3;
                uint32_t abase;
                if (kb == 0)
                    abase = sb + (tva[t_] ? SX_LO : SX_HI)
                          + (wm * 16 + (lane & 15)) * 144 + (lane >> 4) * 16;
                else
                    abase = sb + h_rd + (tva[t_] ? 8704u : 0u)
                          + (wm * 16 + (lane & 15)) * 272 + (lane >> 4) * 16
                          + (kb - 1) * 128;
                uint32_t bbase = sb + SB + buf * 18432
                               + (wn * 32 + (lane & 7)) * 144 + ((lane >> 3) & 1) * 16;

#pragma unroll
                for (int ks = 0; ks < 4; ks++) {
                    uint32_t a[4], bfr[4][2];
                    ldm_x4(a, abase + ks * 32);
#pragma unroll
                    for (int nt = 0; nt < 4; nt++)
                        ldm_x2(bfr[nt], bbase + nt * (8 * 144) + ks * 32);
#pragma unroll
                    for (int nt = 0; nt < 4; nt++)
                        mma_bf16(acc[nt], a, bfr[nt]);
                }
                __syncthreads();
            }

            // LSTM epilogue for this n-chunk (shfl gate-pair exchange)
#pragma unroll
            for (int nt = 0; nt < 4; nt++) {
                int col = nc * 128 + wn * 32 + nt * 8 + (lane & 3) * 2;
                float b0 = __ldg(&d_bias[col]);
                float b1 = __ldg(&d_bias[col + 1]);
                float a0 = acc[nt][0] + b0, a1 = acc[nt][1] + b1;
                float a2 = acc[nt][2] + b0, a3 = acc[nt][3] + b1;
                float p0 = __shfl_xor_sync(0xffffffffu, a0, 1);
                float p1 = __shfl_xor_sync(0xffffffffu, a1, 1);
                float p2 = __shfl_xor_sync(0xffffffffu, a2, 1);
                float p3 = __shfl_xor_sync(0xffffffffu, a3, 1);
                if (!(lane & 1)) {
                    int j = (col >> 2);                // global j in 0..127
                    int row = wm * 16 + (lane >> 2);
#pragma unroll
                    for (int hh = 0; hh < 2; hh++) {
                        int rr = row + hh * 8;
                        float gi = hh ? a2 : a0;
                        float gf = hh ? a3 : a1;
                        float gg = hh ? p2 : p0;
                        float go = hh ? p3 : p1;
                        float co = s_c[rr * 128 + j];
                        float si = 1.0f / (1.0f + expf(-gi));
                        float sf = 1.0f / (1.0f + expf(-gf));
                        float so = 1.0f / (1.0f + expf(-go));
                        float cn = sf * co + si * tanhf(gg);
                        float hn = so * tanhf(cn);
                        s_c[rr * 128 + j] = cn;
                        __nv_bfloat16 hhi = __float2bfloat16(hn);
                        s_hhi_w[rr * 136 + j] = hhi;
                        s_hlo_w[rr * 136 + j] = __float2bfloat16(hn - __bfloat162float(hhi));
                        if (t == NSTEP - 1)
                            out[(bm0 + rr) * 128 + j] = hn;
                    }
                }
            }
        }
#undef LOAD_B
        __syncthreads();
    }
#undef ISSUE_IMG
}

// ---------------- launch ----------------------------------------------------
extern "C" void kernel_launch(void* const* d_in, const int* in_sizes, int n_in,
                              void* d_out, int out_size)
{
    const float* imgs = (const float*)d_in[0];
    const float* W_ih = (const float*)d_in[1];
    const float* W_hh = (const float*)d_in[2];
    const float* b_ih = (const float*)d_in[3];
    const float* b_hh = (const float*)d_in[4];
    const float* W_g  = (const float*)d_in[5];
    const float* b_g  = (const float*)d_in[6];
    float* out = (float*)d_out;

    static int smem_set = 0;
    if (!smem_set) {
        cudaFuncSetAttribute(arc_kernel,
                             cudaFuncAttributeMaxDynamicSharedMemorySize, SM_TOTAL);
        smem_set = 1;
    }

    prologue_kernel<<<8576, 256>>>(imgs, W_ih, W_hh, b_ih, b_hh);
    arc_kernel<<<BATCH / 32, 256, SM_TOTAL>>>(out, W_g, b_g);
}

// round 15
// speedup vs baseline: 1.1241x; 1.1241x over previous
#include <cuda_runtime.h>
#include <cuda_bf16.h>
#include <cuda_fp16.h>
#include <math.h>
#include <stdint.h>

#define BATCH 4096
#define HID 128
#define NSTEP 16

// ---------------- global data (device globals; no allocations) ---------------
__device__ __align__(16) __nv_bfloat16 d_W_hi[512 * 192];   // reordered cols: n' = j*4+gate
__device__ __align__(16) __nv_bfloat16 d_W_lo[512 * 192];
__device__ __align__(16) float d_bias[512];                  // reordered
__device__ __align__(16) __half d_img_h[(size_t)BATCH * 2 * 4096];  // fp16 images (67MB)

// ---------------- smem layout (bytes) ----------------------------------------
// x:  [32][72] bf16, stride 144: hi @0, lo @4608
// h:  ping-pong bufs (read t&1, write (t+1)&1): buf k @ 9216+k*17408 (hi), +8704 (lo)
//     [32][136] bf16, stride 272
// c:  [32][128] f32 @44032
// img: 8 warps x 2 bufs x 8192 @60416 (phase G only)
// filt: 8 warps x 4608 @191488 (phase G only)
// B (phase M only, overlays img): 8 warps x 2 bufs x 9216 @60416  (ends 207872)
#define SX_HI   0
#define SX_LO   4608
#define SH0     9216
#define HBUF    17408
#define SC      44032
#define SIMG    60416
#define SB2     60416
#define SFILT   191488
#define SM_TOTAL 228352

// ---------------- helpers ----------------------------------------------------
__device__ __forceinline__ uint32_t smem_u32(const void* p) {
    uint32_t a;
    asm("{ .reg .u64 t; cvta.to.shared.u64 t, %1; cvt.u32.u64 %0, t; }" : "=r"(a) : "l"(p));
    return a;
}
__device__ __forceinline__ void cp_async16(uint32_t dst, const void* src) {
    asm volatile("cp.async.cg.shared.global [%0], [%1], 16;" :: "r"(dst), "l"(src) : "memory");
}
__device__ __forceinline__ void cp_commit() {
    asm volatile("cp.async.commit_group;" ::: "memory");
}
template <int N>
__device__ __forceinline__ void cp_wait() {
    asm volatile("cp.async.wait_group %0;" :: "n"(N) : "memory");
}
__device__ __forceinline__ void ldm_x4(uint32_t* r, uint32_t a) {
    asm volatile("ldmatrix.sync.aligned.m8n8.x4.shared.b16 {%0,%1,%2,%3}, [%4];"
                 : "=r"(r[0]), "=r"(r[1]), "=r"(r[2]), "=r"(r[3]) : "r"(a));
}
__device__ __forceinline__ void ldm_x4_t(uint32_t* r, uint32_t a) {
    asm volatile("ldmatrix.sync.aligned.m8n8.x4.trans.shared.b16 {%0,%1,%2,%3}, [%4];"
                 : "=r"(r[0]), "=r"(r[1]), "=r"(r[2]), "=r"(r[3]) : "r"(a));
}
__device__ __forceinline__ void ldm_x2(uint32_t* r, uint32_t a) {
    asm volatile("ldmatrix.sync.aligned.m8n8.x2.shared.b16 {%0,%1}, [%2];"
                 : "=r"(r[0]), "=r"(r[1]) : "r"(a));
}
__device__ __forceinline__ void mma_bf16(float* d, const uint32_t* a, const uint32_t* b) {
    asm volatile(
        "mma.sync.aligned.m16n8k16.row.col.f32.bf16.bf16.f32 "
        "{%0,%1,%2,%3}, {%4,%5,%6,%7}, {%8,%9}, {%0,%1,%2,%3};"
        : "+f"(d[0]), "+f"(d[1]), "+f"(d[2]), "+f"(d[3])
        : "r"(a[0]), "r"(a[1]), "r"(a[2]), "r"(a[3]), "r"(b[0]), "r"(b[1]));
}
__device__ __forceinline__ void mma_f16(float* d, const uint32_t* a, const uint32_t* b) {
    asm volatile(
        "mma.sync.aligned.m16n8k16.row.col.f32.f16.f16.f32 "
        "{%0,%1,%2,%3}, {%4,%5,%6,%7}, {%8,%9}, {%0,%1,%2,%3};"
        : "+f"(d[0]), "+f"(d[1]), "+f"(d[2]), "+f"(d[3])
        : "r"(a[0]), "r"(a[1]), "r"(a[2]), "r"(a[3]), "r"(b[0]), "r"(b[1]));
}
__device__ __forceinline__ uint32_t pack_h2(float x, float y) {
    __half2 h = __floats2half2_rn(x, y);
    return *reinterpret_cast<uint32_t*>(&h);
}

// ---------------- prologue ---------------------------------------------------
__global__ void prologue_kernel(const float* __restrict__ imgs,
                                const float* __restrict__ W_ih,
                                const float* __restrict__ W_hh,
                                const float* __restrict__ b_ih,
                                const float* __restrict__ b_hh) {
    int bid = blockIdx.x, tid = threadIdx.x;
    if (bid < 8192) {
        const float4* in4 = reinterpret_cast<const float4*>(imgs);
        uint2* out2 = reinterpret_cast<uint2*>(d_img_h);
        for (int i = bid * 256 + tid; i < 8388608; i += 8192 * 256) {
            float4 v = in4[i];
            __half2 a = __floats2half2_rn(v.x, v.y);
            __half2 c = __floats2half2_rn(v.z, v.w);
            uint2 o;
            o.x = *reinterpret_cast<uint32_t*>(&a);
            o.y = *reinterpret_cast<uint32_t*>(&c);
            out2[i] = o;
        }
    } else {
        int idx = (bid - 8192) * 256 + tid;  // exactly 512*192
        int np = idx / 192, k = idx % 192;
        int gate = np & 3, j = np >> 2;
        int orig = gate * 128 + j;
        float w = (k < 64) ? W_ih[orig * 64 + k] : W_hh[orig * 128 + (k - 64)];
        __nv_bfloat16 hi = __float2bfloat16(w);
        __nv_bfloat16 lo = __float2bfloat16(w - __bfloat162float(hi));
        d_W_hi[np * 192 + k] = hi;
        d_W_lo[np * 192 + k] = lo;
        if (k == 0) d_bias[np] = b_ih[orig] + b_hh[orig];
    }
}

// ---------------- persistent mega kernel -------------------------------------
// 128 CTAs x 256 threads. CTA owns 32 samples for all 16 steps.
// Phase G: per-warp tensor-core glimpse (4 samples/warp, image double-buffer).
// Phase M: per-warp gates GEMM (warp owns 64 of 512 cols; own B slices;
//          NO CTA barriers) + fused LSTM. h ping-pong by step parity.
__global__ __launch_bounds__(256) void arc_kernel(
    float* __restrict__ out,
    const float* __restrict__ W_g, const float* __restrict__ b_g)
{
    extern __shared__ char sm[];
    uint32_t sb = smem_u32(sm);
    int tid = threadIdx.x, wid = tid >> 5, lane = tid & 31;
    int bm0 = blockIdx.x * 32;

    __nv_bfloat16* s_xhi = reinterpret_cast<__nv_bfloat16*>(sm + SX_HI);
    __nv_bfloat16* s_xlo = reinterpret_cast<__nv_bfloat16*>(sm + SX_LO);
    float* s_c = reinterpret_cast<float*>(sm + SC);

    const int tva[3] = {0, 0, 1};
    const int tvb[3] = {0, 1, 0};

    // zero state (x, both h buffers, c)
    for (int i = tid; i < 60416 / 4; i += 256)
        reinterpret_cast<float*>(sm)[i] = 0.0f;

#define ISSUE_IMG(pbuf, smp, selv) do {                                          \
        const __half* src_ = d_img_h + ((size_t)(smp) * 2 + (size_t)(selv)) * 4096; \
        uint32_t dst_ = sb + SIMG + (wid * 2 + (pbuf)) * 8192;                   \
        _Pragma("unroll")                                                        \
        for (int j_ = 0; j_ < 16; j_++) {                                        \
            int cc_ = lane + j_ * 32;                                            \
            int rr_ = cc_ >> 3, ch_ = cc_ & 7;                                   \
            cp_async16(dst_ + rr_ * 128 + ((ch_ ^ (rr_ & 7)) * 16),              \
                       src_ + rr_ * 64 + ch_ * 8);                               \
        }                                                                        \
        cp_commit();                                                             \
    } while (0)

    __syncthreads();

    for (int t = 0; t < NSTEP; t++) {
        int sel = t & 1;
        uint32_t h_rd = (uint32_t)(SH0 + (t & 1) * HBUF);
        uint32_t h_wr = (uint32_t)(SH0 + ((t + 1) & 1) * HBUF);
        __nv_bfloat16* s_hhi_w = reinterpret_cast<__nv_bfloat16*>(sm + h_wr);
        __nv_bfloat16* s_hlo_w = reinterpret_cast<__nv_bfloat16*>(sm + h_wr + 8704);

        // ================= phase G: glimpse (per-warp, 4 rounds) =============
        uint32_t filtb = sb + SFILT + wid * 4608;
        ISSUE_IMG(0, bm0 + wid * 4, sel);   // round-0 image
        for (int r = 0; r < 4; r++) {
            int s_loc = wid * 4 + r;
            int pbuf = r & 1;
            if (r < 3) ISSUE_IMG(pbuf ^ 1, bm0 + s_loc + 1, sel);

            // gp = tanh(h @ W_g^T + b_g)
            float h4[4];
            {
                uint2 rhu = *reinterpret_cast<uint2*>(sm + h_rd + s_loc * 272 + lane * 8);
                uint2 rlu = *reinterpret_cast<uint2*>(sm + h_rd + 8704 + s_loc * 272 + lane * 8);
                __nv_bfloat162* hh = reinterpret_cast<__nv_bfloat162*>(&rhu);
                __nv_bfloat162* ll = reinterpret_cast<__nv_bfloat162*>(&rlu);
                float2 h01 = __bfloat1622float2(hh[0]);
                float2 h23 = __bfloat1622float2(hh[1]);
                float2 l01 = __bfloat1622float2(ll[0]);
                float2 l23 = __bfloat1622float2(ll[1]);
                h4[0] = h01.x + l01.x; h4[1] = h01.y + l01.y;
                h4[2] = h23.x + l23.x; h4[3] = h23.y + l23.y;
            }
            float gp[3];
#pragma unroll
            for (int k = 0; k < 3; k++) {
                float4 wv = __ldg(reinterpret_cast<const float4*>(&W_g[k * 128 + lane * 4]));
                float p = h4[0] * wv.x + h4[1] * wv.y + h4[2] * wv.z + h4[3] * wv.w;
#pragma unroll
                for (int o = 16; o > 0; o >>= 1) p += __shfl_xor_sync(0xffffffffu, p, o);
                gp[k] = tanhf(p + __ldg(&b_g[k]));
            }

            // normalized Cauchy filterbanks, fp16 hi/lo
            {
                float ad  = fabsf(gp[2]);
                float dlt = 8.0f * (1.0f - ad);
                float gam = expf(1.0f - 2.0f * ad);
                float ig  = 1.0f / gam;
                float cpre = 1.0f / (3.14159265358979323f * gam);
                float fi0 = (float)(2 * lane), fi1 = fi0 + 1.0f;
#pragma unroll
                for (int a = 0; a < 2; a++) {
                    float center = 31.5f * (gp[a] + 1.0f);
                    uint32_t base = filtb + (a ? 2304u : 0u);
#pragma unroll
                    for (int tt = 0; tt < 8; tt++) {
                        float gpix = center + dlt * ((float)tt - 3.5f);
                        float u0 = (fi0 - gpix) * ig, u1 = (fi1 - gpix) * ig;
                        float v0 = __fdividef(cpre, 1.0f + u0 * u0);
                        float v1 = __fdividef(cpre, 1.0f + u1 * u1);
                        float s = v0 + v1;
#pragma unroll
                        for (int o = 16; o > 0; o >>= 1) s += __shfl_xor_sync(0xffffffffu, s, o);
                        float inv = __fdividef(1.0f, s + 1e-4f);
                        v0 *= inv; v1 *= inv;
                        uint32_t hi2 = pack_h2(v0, v1);
                        __half2 hh2 = *reinterpret_cast<__half2*>(&hi2);
                        float2 hf = __half22float2(hh2);
                        uint32_t lo2 = pack_h2(v0 - hf.x, v1 - hf.y);
                        uint32_t dst = base + tt * 144 + lane * 4;
                        asm volatile("st.shared.b32 [%0], %1;" :: "r"(dst), "r"(hi2));
                        asm volatile("st.shared.b32 [%0], %1;" :: "r"(dst + 1152), "r"(lo2));
                    }
                }
            }
            if (r < 3) cp_wait<1>(); else cp_wait<0>();
            __syncwarp();

            // G1
            float acc[8][4];
#pragma unroll
            for (int nt = 0; nt < 8; nt++)
#pragma unroll
                for (int q = 0; q < 4; q++) acc[nt][q] = 0.0f;

            uint32_t fh = filtb + (lane & 15) * 144 + (lane >> 4) * 16;
            uint32_t ibuf = sb + SIMG + (wid * 2 + pbuf) * 8192 + (lane & 15) * 128;
            int cb = lane >> 4, xorv = lane & 7;

#pragma unroll
            for (int kk = 0; kk < 4; kk++) {
                uint32_t ah[4];
                ldm_x4(ah, fh + kk * 32);
#pragma unroll
                for (int nt2 = 0; nt2 < 4; nt2++) {
                    uint32_t bb[4];
                    uint32_t ch = (uint32_t)(((2 * nt2 + cb) ^ xorv) * 16);
                    ldm_x4_t(bb, ibuf + kk * 2048 + ch);
                    mma_f16(acc[2 * nt2],     ah, bb);
                    mma_f16(acc[2 * nt2 + 1], ah, bb + 2);
                }
            }

            float ps[8][2];
#pragma unroll
            for (int nt = 0; nt < 8; nt++) {
                ps[nt][0] = acc[nt][0] + acc[nt][2];
                ps[nt][1] = acc[nt][1] + acc[nt][3];
            }

            // G2
            float acc2[4] = {0.0f, 0.0f, 0.0f, 0.0f};
            uint32_t fwb = filtb + 2304 + (lane & 7) * 144 + ((lane >> 3) & 1) * 16;
#pragma unroll
            for (int kk2 = 0; kk2 < 4; kk2++) {
                float p0 = ps[2 * kk2][0],     p1 = ps[2 * kk2][1];
                float q0 = ps[2 * kk2 + 1][0], q1 = ps[2 * kk2 + 1][1];
                uint32_t ah[4], al[4];
                ah[0] = pack_h2(p0, p1);
                ah[2] = pack_h2(q0, q1);
                ah[1] = 0u; ah[3] = 0u;
                {
                    __half2 h0 = *reinterpret_cast<__half2*>(&ah[0]);
                    __half2 h2 = *reinterpret_cast<__half2*>(&ah[2]);
                    float2 f0 = __half22float2(h0);
                    float2 f2 = __half22float2(h2);
                    al[0] = pack_h2(p0 - f0.x, p1 - f0.y);
                    al[2] = pack_h2(q0 - f2.x, q1 - f2.y);
                    al[1] = 0u; al[3] = 0u;
                }
                uint32_t bh[2], bl[2];
                ldm_x2(bh, fwb + kk2 * 32);
                ldm_x2(bl, fwb + 1152 + kk2 * 32);
                mma_f16(acc2, ah, bh);
                mma_f16(acc2, al, bh);
                mma_f16(acc2, ah, bl);
            }

            // write x
            {
                int c8 = (lane >> 2) * 8 + (lane & 3) * 2;
                float v0 = acc2[0], v1 = acc2[1];
                __nv_bfloat16 h0 = __float2bfloat16(v0);
                __nv_bfloat16 h1 = __float2bfloat16(v1);
                s_xhi[s_loc * 72 + c8]     = h0;
                s_xhi[s_loc * 72 + c8 + 1] = h1;
                s_xlo[s_loc * 72 + c8]     = __float2bfloat16(v0 - __bfloat162float(h0));
                s_xlo[s_loc * 72 + c8 + 1] = __float2bfloat16(v1 - __bfloat162float(h1));
            }
        }
        __syncthreads();   // x/h complete; img+filt become dead -> B overlays

        // ================= phase M: per-warp GEMM (NO CTA barriers) ==========
        // warp wid owns cols [wid*64, wid*64+64); rows = all 32.
#define LOAD_BW(c9v, bufv) do {                                                  \
        int t2_ = (c9v) / 3, kb2_ = (c9v) % 3;                                   \
        const __nv_bfloat16* ws_ = tvb[t2_] ? d_W_lo : d_W_hi;                   \
        _Pragma("unroll")                                                        \
        for (int p_ = 0; p_ < 16; p_++) {                                        \
            int ix_ = lane + p_ * 32;                                            \
            int rw_ = ix_ >> 3, cc_ = ix_ & 7;                                   \
            cp_async16(sb + SB2 + (wid * 2 + (bufv)) * 9216 + rw_ * 144 + cc_ * 16, \
                       ws_ + (wid * 64 + rw_) * 192 + kb2_ * 64 + cc_ * 8);      \
        }                                                                        \
        cp_commit();                                                             \
    } while (0)

        float mac[2][8][4];
#pragma unroll
        for (int mt = 0; mt < 2; mt++)
#pragma unroll
            for (int nt = 0; nt < 8; nt++)
#pragma unroll
                for (int q = 0; q < 4; q++) mac[mt][nt][q] = 0.0f;

        LOAD_BW(0, 0);
        for (int c9 = 0; c9 < 9; c9++) {
            int buf = c9 & 1;
            if (c9 < 8) LOAD_BW(c9 + 1, buf ^ 1);
            if (c9 < 8) cp_wait<1>(); else cp_wait<0>();
            __syncwarp();

            int t_ = c9 / 3, kb = c9 % 3;
            uint32_t abase0, astride;
            if (kb == 0) {
                abase0 = sb + (tva[t_] ? SX_LO : SX_HI)
                       + (lane & 15) * 144 + (lane >> 4) * 16;
                astride = 16 * 144;
            } else {
                abase0 = sb + h_rd + (tva[t_] ? 8704u : 0u)
                       + (lane & 15) * 272 + (lane >> 4) * 16 + (kb - 1) * 128;
                astride = 16 * 272;
            }
            uint32_t bbase = sb + SB2 + (wid * 2 + buf) * 9216
                           + (lane & 7) * 144 + ((lane >> 3) & 1) * 16;

#pragma unroll
            for (int ks = 0; ks < 4; ks++) {
                uint32_t a[2][4], bfr[8][2];
                ldm_x4(a[0], abase0 + ks * 32);
                ldm_x4(a[1], abase0 + astride + ks * 32);
#pragma unroll
                for (int nt = 0; nt < 8; nt++)
                    ldm_x2(bfr[nt], bbase + nt * (8 * 144) + ks * 32);
#pragma unroll
                for (int mt = 0; mt < 2; mt++)
#pragma unroll
                    for (int nt = 0; nt < 8; nt++)
                        mma_bf16(mac[mt][nt], a[mt], bfr[nt]);
            }
        }
#undef LOAD_BW

        // LSTM epilogue (warp-exclusive j range [wid*16, wid*16+16))
#pragma unroll
        for (int mt = 0; mt < 2; mt++)
#pragma unroll
            for (int nt = 0; nt < 8; nt++) {
                int col = wid * 64 + nt * 8 + (lane & 3) * 2;
                float b0 = __ldg(&d_bias[col]);
                float b1 = __ldg(&d_bias[col + 1]);
                float a0 = mac[mt][nt][0] + b0, a1 = mac[mt][nt][1] + b1;
                float a2 = mac[mt][nt][2] + b0, a3 = mac[mt][nt][3] + b1;
                float p0 = __shfl_xor_sync(0xffffffffu, a0, 1);
                float p1 = __shfl_xor_sync(0xffffffffu, a1, 1);
                float p2 = __shfl_xor_sync(0xffffffffu, a2, 1);
                float p3 = __shfl_xor_sync(0xffffffffu, a3, 1);
                if (!(lane & 1)) {
                    int j = (col >> 2);
                    int row = mt * 16 + (lane >> 2);
#pragma unroll
                    for (int hh = 0; hh < 2; hh++) {
                        int rr = row + hh * 8;
                        float gi = hh ? a2 : a0;
                        float gf = hh ? a3 : a1;
                        float gg = hh ? p2 : p0;
                        float go = hh ? p3 : p1;
                        float co = s_c[rr * 128 + j];
                        float si = 1.0f / (1.0f + expf(-gi));
                        float sf = 1.0f / (1.0f + expf(-gf));
                        float so = 1.0f / (1.0f + expf(-go));
                        float cn = sf * co + si * tanhf(gg);
                        float hn = so * tanhf(cn);
                        s_c[rr * 128 + j] = cn;
                        __nv_bfloat16 hhi = __float2bfloat16(hn);
                        s_hhi_w[rr * 136 + j] = hhi;
                        s_hlo_w[rr * 136 + j] = __float2bfloat16(hn - __bfloat162float(hhi));
                        if (t == NSTEP - 1)
                            out[(bm0 + rr) * 128 + j] = hn;
                    }
                }
            }
        __syncthreads();   // h_{t+1} complete; B becomes dead -> img reuses
    }
#undef ISSUE_IMG
}

// ---------------- launch ----------------------------------------------------
extern "C" void kernel_launch(void* const* d_in, const int* in_sizes, int n_in,
                              void* d_out, int out_size)
{
    const float* imgs = (const float*)d_in[0];
    const float* W_ih = (const float*)d_in[1];
    const float* W_hh = (const float*)d_in[2];
    const float* b_ih = (const float*)d_in[3];
    const float* b_hh = (const float*)d_in[4];
    const float* W_g  = (const float*)d_in[5];
    const float* b_g  = (const float*)d_in[6];
    float* out = (float*)d_out;

    static int smem_set = 0;
    if (!smem_set) {
        cudaFuncSetAttribute(arc_kernel,
                             cudaFuncAttributeMaxDynamicSharedMemorySize, SM_TOTAL);
        smem_set = 1;
    }

    prologue_kernel<<<8576, 256>>>(imgs, W_ih, W_hh, b_ih, b_hh);
    arc_kernel<<<BATCH / 32, 256, SM_TOTAL>>>(out, W_g, b_g);
}

// round 16
// speedup vs baseline: 1.3689x; 1.2178x over previous
#include <cuda_runtime.h>
#include <cuda_bf16.h>
#include <cuda_fp16.h>
#include <math.h>
#include <stdint.h>

#define BATCH 4096
#define HID 128
#define NSTEP 16

// ---------------- global data ------------------------------------------------
__device__ __align__(16) __nv_bfloat16 d_W_hi[512 * 192];   // reordered cols: n' = j*4+gate
__device__ __align__(16) __nv_bfloat16 d_W_lo[512 * 192];
__device__ __align__(16) float d_bias[512];                  // reordered
__device__ __align__(16) __half d_img_h[(size_t)BATCH * 2 * 4096];  // fp16 images (67MB)

// ---------------- smem layout (bytes) ----------------------------------------
// x:  [32][72] bf16, stride 144: hi @0, lo @4608
// h:  ping-pong bufs: buf k @ 9216+k*17408 (hi), +8704 (lo); [32][136] bf16, stride 272
// c:  [32][128] f32 @44032
// img: 8 pairs x 2 bufs x 8192 @60416 (phase G)
// filt: 8 pairs x 4608 @191488 (phase G; FhA 16x144 @+0, FwB @+2304: hi 8x144, lo @+1152)
// B (phase M, overlays img+low filt): 16 warps x 2 bufs x 4608 @60416 (ends 207872)
#define SX_HI   0
#define SX_LO   4608
#define SH0     9216
#define HBUF    17408
#define SC      44032
#define SIMG    60416
#define SB2     60416
#define SFILT   191488
#define SM_TOTAL 228352

// ---------------- helpers ----------------------------------------------------
__device__ __forceinline__ uint32_t smem_u32(const void* p) {
    uint32_t a;
    asm("{ .reg .u64 t; cvta.to.shared.u64 t, %1; cvt.u32.u64 %0, t; }" : "=r"(a) : "l"(p));
    return a;
}
__device__ __forceinline__ void cp_async16(uint32_t dst, const void* src) {
    asm volatile("cp.async.cg.shared.global [%0], [%1], 16;" :: "r"(dst), "l"(src) : "memory");
}
__device__ __forceinline__ void cp_commit() {
    asm volatile("cp.async.commit_group;" ::: "memory");
}
template <int N>
__device__ __forceinline__ void cp_wait() {
    asm volatile("cp.async.wait_group %0;" :: "n"(N) : "memory");
}
__device__ __forceinline__ void bar_pair(int id) {
    asm volatile("bar.sync %0, 64;" :: "r"(id) : "memory");
}
__device__ __forceinline__ void ldm_x4(uint32_t* r, uint32_t a) {
    asm volatile("ldmatrix.sync.aligned.m8n8.x4.shared.b16 {%0,%1,%2,%3}, [%4];"
                 : "=r"(r[0]), "=r"(r[1]), "=r"(r[2]), "=r"(r[3]) : "r"(a));
}
__device__ __forceinline__ void ldm_x4_t(uint32_t* r, uint32_t a) {
    asm volatile("ldmatrix.sync.aligned.m8n8.x4.trans.shared.b16 {%0,%1,%2,%3}, [%4];"
                 : "=r"(r[0]), "=r"(r[1]), "=r"(r[2]), "=r"(r[3]) : "r"(a));
}
__device__ __forceinline__ void ldm_x2(uint32_t* r, uint32_t a) {
    asm volatile("ldmatrix.sync.aligned.m8n8.x2.shared.b16 {%0,%1}, [%2];"
                 : "=r"(r[0]), "=r"(r[1]) : "r"(a));
}
__device__ __forceinline__ void mma_bf16(float* d, const uint32_t* a, const uint32_t* b) {
    asm volatile(
        "mma.sync.aligned.m16n8k16.row.col.f32.bf16.bf16.f32 "
        "{%0,%1,%2,%3}, {%4,%5,%6,%7}, {%8,%9}, {%0,%1,%2,%3};"
        : "+f"(d[0]), "+f"(d[1]), "+f"(d[2]), "+f"(d[3])
        : "r"(a[0]), "r"(a[1]), "r"(a[2]), "r"(a[3]), "r"(b[0]), "r"(b[1]));
}
__device__ __forceinline__ void mma_f16(float* d, const uint32_t* a, const uint32_t* b) {
    asm volatile(
        "mma.sync.aligned.m16n8k16.row.col.f32.f16.f16.f32 "
        "{%0,%1,%2,%3}, {%4,%5,%6,%7}, {%8,%9}, {%0,%1,%2,%3};"
        : "+f"(d[0]), "+f"(d[1]), "+f"(d[2]), "+f"(d[3])
        : "r"(a[0]), "r"(a[1]), "r"(a[2]), "r"(a[3]), "r"(b[0]), "r"(b[1]));
}
__device__ __forceinline__ uint32_t pack_h2(float x, float y) {
    __half2 h = __floats2half2_rn(x, y);
    return *reinterpret_cast<uint32_t*>(&h);
}

// ---------------- prologue ---------------------------------------------------
__global__ void prologue_kernel(const float* __restrict__ imgs,
                                const float* __restrict__ W_ih,
                                const float* __restrict__ W_hh,
                                const float* __restrict__ b_ih,
                                const float* __restrict__ b_hh) {
    int bid = blockIdx.x, tid = threadIdx.x;
    if (bid < 8192) {
        const float4* in4 = reinterpret_cast<const float4*>(imgs);
        uint2* out2 = reinterpret_cast<uint2*>(d_img_h);
        for (int i = bid * 256 + tid; i < 8388608; i += 8192 * 256) {
            float4 v = in4[i];
            __half2 a = __floats2half2_rn(v.x, v.y);
            __half2 c = __floats2half2_rn(v.z, v.w);
            uint2 o;
            o.x = *reinterpret_cast<uint32_t*>(&a);
            o.y = *reinterpret_cast<uint32_t*>(&c);
            out2[i] = o;
        }
    } else {
        int idx = (bid - 8192) * 256 + tid;  // exactly 512*192
        int np = idx / 192, k = idx % 192;
        int gate = np & 3, j = np >> 2;
        int orig = gate * 128 + j;
        float w = (k < 64) ? W_ih[orig * 64 + k] : W_hh[orig * 128 + (k - 64)];
        __nv_bfloat16 hi = __float2bfloat16(w);
        __nv_bfloat16 lo = __float2bfloat16(w - __bfloat162float(hi));
        d_W_hi[np * 192 + k] = hi;
        d_W_lo[np * 192 + k] = lo;
        if (k == 0) d_bias[np] = b_ih[orig] + b_hh[orig];
    }
}

// ---------------- persistent mega kernel (512 threads) -----------------------
__global__ __launch_bounds__(512) void arc_kernel(
    float* __restrict__ out,
    const float* __restrict__ W_g, const float* __restrict__ b_g)
{
    extern __shared__ char sm[];
    uint32_t sb = smem_u32(sm);
    int tid = threadIdx.x, wid = tid >> 5, lane = tid & 31;
    int pair = wid >> 1, wh = wid & 1;
    int bar_id = 1 + pair;
    int bm0 = blockIdx.x * 32;

    __nv_bfloat16* s_xhi = reinterpret_cast<__nv_bfloat16*>(sm + SX_HI);
    __nv_bfloat16* s_xlo = reinterpret_cast<__nv_bfloat16*>(sm + SX_LO);
    float* s_c = reinterpret_cast<float*>(sm + SC);

    const int tva[3] = {0, 0, 1};
    const int tvb[3] = {0, 1, 0};

    for (int i = tid; i < 60416 / 4; i += 512)
        reinterpret_cast<float*>(sm)[i] = 0.0f;

    // pair-cooperative image load (each warp half the tile)
#define ISSUE_IMG(pbuf, smp, selv) do {                                          \
        const __half* src_ = d_img_h + ((size_t)(smp) * 2 + (size_t)(selv)) * 4096; \
        uint32_t dst_ = sb + SIMG + (pair * 2 + (pbuf)) * 8192;                  \
        _Pragma("unroll")                                                        \
        for (int j_ = 0; j_ < 8; j_++) {                                         \
            int cc_ = wh * 256 + lane + j_ * 32;                                 \
            int rr_ = cc_ >> 3, ch_ = cc_ & 7;                                   \
            cp_async16(dst_ + rr_ * 128 + ((ch_ ^ (rr_ & 7)) * 16),              \
                       src_ + rr_ * 64 + ch_ * 8);                               \
        }                                                                        \
        cp_commit();                                                             \
    } while (0)

    __syncthreads();

    for (int t = 0; t < NSTEP; t++) {
        int sel = t & 1;
        uint32_t h_rd = (uint32_t)(SH0 + (t & 1) * HBUF);
        uint32_t h_wr = (uint32_t)(SH0 + ((t + 1) & 1) * HBUF);
        __nv_bfloat16* s_hhi_w = reinterpret_cast<__nv_bfloat16*>(sm + h_wr);
        __nv_bfloat16* s_hlo_w = reinterpret_cast<__nv_bfloat16*>(sm + h_wr + 8704);

        // ===== phase G: pair handles 4 samples (4 rounds) ====================
        uint32_t filtb = sb + SFILT + pair * 4608;
        ISSUE_IMG(0, bm0 + pair * 4, sel);
        for (int r = 0; r < 4; r++) {
            int s_loc = pair * 4 + r;
            int pbuf = r & 1;
            if (r < 3) ISSUE_IMG(pbuf ^ 1, bm0 + s_loc + 1, sel);

            // gp = tanh(h @ W_g^T + b_g)
            float h4[4];
            {
                uint2 rhu = *reinterpret_cast<uint2*>(sm + h_rd + s_loc * 272 + lane * 8);
                uint2 rlu = *reinterpret_cast<uint2*>(sm + h_rd + 8704 + s_loc * 272 + lane * 8);
                __nv_bfloat162* hh = reinterpret_cast<__nv_bfloat162*>(&rhu);
                __nv_bfloat162* ll = reinterpret_cast<__nv_bfloat162*>(&rlu);
                float2 h01 = __bfloat1622float2(hh[0]);
                float2 h23 = __bfloat1622float2(hh[1]);
                float2 l01 = __bfloat1622float2(ll[0]);
                float2 l23 = __bfloat1622float2(ll[1]);
                h4[0] = h01.x + l01.x; h4[1] = h01.y + l01.y;
                h4[2] = h23.x + l23.x; h4[3] = h23.y + l23.y;
            }
            float gpa, gp2;   // gpa = gp[wh] (own bank center), gp2 = gp[2]
            {
                float pa, p2;
                {
                    float4 wv = __ldg(reinterpret_cast<const float4*>(&W_g[wh * 128 + lane * 4]));
                    pa = h4[0] * wv.x + h4[1] * wv.y + h4[2] * wv.z + h4[3] * wv.w;
                }
                {
                    float4 wv = __ldg(reinterpret_cast<const float4*>(&W_g[2 * 128 + lane * 4]));
                    p2 = h4[0] * wv.x + h4[1] * wv.y + h4[2] * wv.z + h4[3] * wv.w;
                }
#pragma unroll
                for (int o = 16; o > 0; o >>= 1) {
                    pa += __shfl_xor_sync(0xffffffffu, pa, o);
                    p2 += __shfl_xor_sync(0xffffffffu, p2, o);
                }
                gpa = tanhf(pa + __ldg(&b_g[wh]));
                gp2 = tanhf(p2 + __ldg(&b_g[2]));
            }

            // own filter bank (warp0: Fh, warp1: Fw), normalized, fp16 hi/lo
            {
                float ad  = fabsf(gp2);
                float dlt = 8.0f * (1.0f - ad);
                float gam = expf(1.0f - 2.0f * ad);
                float ig  = 1.0f / gam;
                float cpre = 1.0f / (3.14159265358979323f * gam);
                float fi0 = (float)(2 * lane), fi1 = fi0 + 1.0f;
                float center = 31.5f * (gpa + 1.0f);
                uint32_t base = filtb + (wh ? 2304u : 0u);
#pragma unroll
                for (int tt = 0; tt < 8; tt++) {
                    float gpix = center + dlt * ((float)tt - 3.5f);
                    float u0 = (fi0 - gpix) * ig, u1 = (fi1 - gpix) * ig;
                    float v0 = __fdividef(cpre, 1.0f + u0 * u0);
                    float v1 = __fdividef(cpre, 1.0f + u1 * u1);
                    float s = v0 + v1;
#pragma unroll
                    for (int o = 16; o > 0; o >>= 1) s += __shfl_xor_sync(0xffffffffu, s, o);
                    float inv = __fdividef(1.0f, s + 1e-4f);
                    v0 *= inv; v1 *= inv;
                    uint32_t hi2 = pack_h2(v0, v1);
                    __half2 hh2 = *reinterpret_cast<__half2*>(&hi2);
                    float2 hf = __half22float2(hh2);
                    uint32_t lo2 = pack_h2(v0 - hf.x, v1 - hf.y);
                    uint32_t dst = base + tt * 144 + lane * 4;
                    asm volatile("st.shared.b32 [%0], %1;" :: "r"(dst), "r"(hi2));
                    asm volatile("st.shared.b32 [%0], %1;" :: "r"(dst + 1152), "r"(lo2));
                }
            }
            if (r < 3) cp_wait<1>(); else cp_wait<0>();
            bar_pair(bar_id);   // filters (both banks) + image (both halves) ready

            // G1: warp handles image-column half [wh*32, wh*32+32)
            float accL[4][4];
#pragma unroll
            for (int nt = 0; nt < 4; nt++)
#pragma unroll
                for (int q = 0; q < 4; q++) accL[nt][q] = 0.0f;

            uint32_t fh = filtb + (lane & 15) * 144 + (lane >> 4) * 16;
            uint32_t ibuf = sb + SIMG + (pair * 2 + pbuf) * 8192 + (lane & 15) * 128;
            int cb = lane >> 4, xorv = lane & 7;

#pragma unroll
            for (int kk = 0; kk < 4; kk++) {
                uint32_t ah[4];
                ldm_x4(ah, fh + kk * 32);
#pragma unroll
                for (int ntl = 0; ntl < 2; ntl++) {
                    int nt2 = 2 * wh + ntl;
                    uint32_t bb[4];
                    uint32_t ch = (uint32_t)(((2 * nt2 + cb) ^ xorv) * 16);
                    ldm_x4_t(bb, ibuf + kk * 2048 + ch);
                    mma_f16(accL[2 * ntl],     ah, bb);
                    mma_f16(accL[2 * ntl + 1], ah, bb + 2);
                }
            }
            float psL[4][2];
#pragma unroll
            for (int nt = 0; nt < 4; nt++) {
                psL[nt][0] = accL[nt][0] + accL[nt][2];
                psL[nt][1] = accL[nt][1] + accL[nt][3];
            }

            // G2: warp handles K-chunks kk2 = 2wh + {0,1}; partial x
            float acc2[4] = {0.0f, 0.0f, 0.0f, 0.0f};
            uint32_t fwb = filtb + 2304 + (lane & 7) * 144 + ((lane >> 3) & 1) * 16;
#pragma unroll
            for (int kl = 0; kl < 2; kl++) {
                int kk2 = 2 * wh + kl;
                float p0 = psL[2 * kl][0],     p1 = psL[2 * kl][1];
                float q0 = psL[2 * kl + 1][0], q1 = psL[2 * kl + 1][1];
                uint32_t ah[4], al[4];
                ah[0] = pack_h2(p0, p1);
                ah[2] = pack_h2(q0, q1);
                ah[1] = 0u; ah[3] = 0u;
                {
                    __half2 h0 = *reinterpret_cast<__half2*>(&ah[0]);
                    __half2 h2 = *reinterpret_cast<__half2*>(&ah[2]);
                    float2 f0 = __half22float2(h0);
                    float2 f2 = __half22float2(h2);
                    al[0] = pack_h2(p0 - f0.x, p1 - f0.y);
                    al[2] = pack_h2(q0 - f2.x, q1 - f2.y);
                    al[1] = 0u; al[3] = 0u;
                }
                uint32_t bh[2], bl[2];
                ldm_x2(bh, fwb + kk2 * 32);
                ldm_x2(bl, fwb + 1152 + kk2 * 32);
                mma_f16(acc2, ah, bh);
                mma_f16(acc2, al, bh);
                mma_f16(acc2, ah, bl);
            }

            bar_pair(bar_id);   // G1/G2 smem reads done; FhA now dead
            if (wh == 1) {
                asm volatile("st.shared.v2.f32 [%0], {%1, %2};"
                             :: "r"(filtb + lane * 8), "f"(acc2[0]), "f"(acc2[1]) : "memory");
            }
            bar_pair(bar_id);
            if (wh == 0) {
                float o0, o1;
                asm volatile("ld.shared.v2.f32 {%0, %1}, [%2];"
                             : "=f"(o0), "=f"(o1) : "r"(filtb + lane * 8));
                float v0 = acc2[0] + o0, v1 = acc2[1] + o1;
                int c8 = (lane >> 2) * 8 + (lane & 3) * 2;
                __nv_bfloat16 h0 = __float2bfloat16(v0);
                __nv_bfloat16 h1 = __float2bfloat16(v1);
                s_xhi[s_loc * 72 + c8]     = h0;
                s_xhi[s_loc * 72 + c8 + 1] = h1;
                s_xlo[s_loc * 72 + c8]     = __float2bfloat16(v0 - __bfloat162float(h0));
                s_xlo[s_loc * 72 + c8 + 1] = __float2bfloat16(v1 - __bfloat162float(h1));
            }
        }
        __syncthreads();   // x complete; img+filt dead -> B overlays

        // ===== phase M: per-warp GEMM, warp owns cols [wid*32, +32) ==========
#define LOAD_BW(c9v, bufv) do {                                                  \
        int t2_ = (c9v) / 3, kb2_ = (c9v) % 3;                                   \
        const __nv_bfloat16* ws_ = tvb[t2_] ? d_W_lo : d_W_hi;                   \
        _Pragma("unroll")                                                        \
        for (int p_ = 0; p_ < 8; p_++) {                                         \
            int ix_ = lane + p_ * 32;                                            \
            int rw_ = ix_ >> 3, cc_ = ix_ & 7;                                   \
            cp_async16(sb + SB2 + (wid * 2 + (bufv)) * 4608 + rw_ * 144 + cc_ * 16, \
                       ws_ + (wid * 32 + rw_) * 192 + kb2_ * 64 + cc_ * 8);      \
        }                                                                        \
        cp_commit();                                                             \
    } while (0)

        float mac[2][4][4];
#pragma unroll
        for (int mt = 0; mt < 2; mt++)
#pragma unroll
            for (int nt = 0; nt < 4; nt++)
#pragma unroll
                for (int q = 0; q < 4; q++) mac[mt][nt][q] = 0.0f;

        LOAD_BW(0, 0);
        for (int c9 = 0; c9 < 9; c9++) {
            int buf = c9 & 1;
            if (c9 < 8) LOAD_BW(c9 + 1, buf ^ 1);
            if (c9 < 8) cp_wait<1>(); else cp_wait<0>();
            __syncwarp();

            int t_ = c9 / 3, kb = c9 % 3;
            uint32_t abase0, astride;
            if (kb == 0) {
                abase0 = sb + (tva[t_] ? SX_LO : SX_HI)
                       + (lane & 15) * 144 + (lane >> 4) * 16;
                astride = 16 * 144;
            } else {
                abase0 = sb + h_rd + (tva[t_] ? 8704u : 0u)
                       + (lane & 15) * 272 + (lane >> 4) * 16 + (kb - 1) * 128;
                astride = 16 * 272;
            }
            uint32_t bbase = sb + SB2 + (wid * 2 + buf) * 4608
                           + (lane & 7) * 144 + ((lane >> 3) & 1) * 16;

#pragma unroll
            for (int ks = 0; ks < 4; ks++) {
                uint32_t a[2][4], bfr[4][2];
                ldm_x4(a[0], abase0 + ks * 32);
                ldm_x4(a[1], abase0 + astride + ks * 32);
#pragma unroll
                for (int nt = 0; nt < 4; nt++)
                    ldm_x2(bfr[nt], bbase + nt * (8 * 144) + ks * 32);
#pragma unroll
                for (int mt = 0; mt < 2; mt++)
#pragma unroll
                    for (int nt = 0; nt < 4; nt++)
                        mma_bf16(mac[mt][nt], a[mt], bfr[nt]);
            }
        }
#undef LOAD_BW

        // LSTM epilogue (warp-exclusive j range [wid*8, wid*8+8))
#pragma unroll
        for (int mt = 0; mt < 2; mt++)
#pragma unroll
            for (int nt = 0; nt < 4; nt++) {
                int col = wid * 32 + nt * 8 + (lane & 3) * 2;
                float b0 = __ldg(&d_bias[col]);
                float b1 = __ldg(&d_bias[col + 1]);
                float a0 = mac[mt][nt][0] + b0, a1 = mac[mt][nt][1] + b1;
                float a2 = mac[mt][nt][2] + b0, a3 = mac[mt][nt][3] + b1;
                float p0 = __shfl_xor_sync(0xffffffffu, a0, 1);
                float p1 = __shfl_xor_sync(0xffffffffu, a1, 1);
                float p2 = __shfl_xor_sync(0xffffffffu, a2, 1);
                float p3 = __shfl_xor_sync(0xffffffffu, a3, 1);
                if (!(lane & 1)) {
                    int j = (col >> 2);
                    int row = mt * 16 + (lane >> 2);
#pragma unroll
                    for (int hh = 0; hh < 2; hh++) {
                        int rr = row + hh * 8;
                        float gi = hh ? a2 : a0;
                        float gf = hh ? a3 : a1;
                        float gg = hh ? p2 : p0;
                        float go = hh ? p3 : p1;
                        float co = s_c[rr * 128 + j];
                        float si = 1.0f / (1.0f + expf(-gi));
                        float sf = 1.0f / (1.0f + expf(-gf));
                        float so = 1.0f / (1.0f + expf(-go));
                        float cn = sf * co + si * tanhf(gg);
                        float hn = so * tanhf(cn);
                        s_c[rr * 128 + j] = cn;
                        __nv_bfloat16 hhi = __float2bfloat16(hn);
                        s_hhi_w[rr * 136 + j] = hhi;
                        s_hlo_w[rr * 136 + j] = __float2bfloat16(hn - __bfloat162float(hhi));
                        if (t == NSTEP - 1)
                            out[(bm0 + rr) * 128 + j] = hn;
                    }
                }
            }
        __syncthreads();   // h_{t+1} complete; B dead -> img reuses
    }
#undef ISSUE_IMG
}

// ---------------- launch ----------------------------------------------------
extern "C" void kernel_launch(void* const* d_in, const int* in_sizes, int n_in,
                              void* d_out, int out_size)
{
    const float* imgs = (const float*)d_in[0];
    const float* W_ih = (const float*)d_in[1];
    const float* W_hh = (const float*)d_in[2];
    const float* b_ih = (const float*)d_in[3];
    const float* b_hh = (const float*)d_in[4];
    const float* W_g  = (const float*)d_in[5];
    const float* b_g  = (const float*)d_in[6];
    float* out = (float*)d_out;

    static int smem_set = 0;
    if (!smem_set) {
        cudaFuncSetAttribute(arc_kernel,
                             cudaFuncAttributeMaxDynamicSharedMemorySize, SM_TOTAL);
        smem_set = 1;
    }

    prologue_kernel<<<8576, 256>>>(imgs, W_ih, W_hh, b_ih, b_hh);
    arc_kernel<<<BATCH / 32, 512, SM_TOTAL>>>(out, W_g, b_g);
}